// round 14
// baseline (speedup 1.0000x reference)
#include <cuda_runtime.h>
#include <cuda_bf16.h>
#include <cstdint>

// DepatchSampling: B=8, C=128, L=4096, P=16, S=8, PC=511, H=64
// R14 = R13 (21.0us) + gather-chain surgery (isolated, memory maps untouched):
//  - magic 2^23 floor: F2I.RD(20cyc) -> FADD.RZ(4)+IADD; I2F removed (wx via fsub)
//  - s_ld parity layout [hb][8]: 8x LDS.64 -> 4x LDS.128 broadcast per lane-iter
//  - store guard hoisted to one per-iter predicate (e==7 only)

#define B_  8
#define C_  128
#define L_  4096
#define P_  16
#define S_  8
#define PC_ 511
#define H_  64

typedef unsigned long long u64t;

__device__ __forceinline__ u64t pack2(float lo, float hi) {
    u64t r; asm("mov.b64 %0, {%1, %2};" : "=l"(r) : "f"(lo), "f"(hi)); return r;
}
__device__ __forceinline__ void unpack2(u64t v, float& lo, float& hi) {
    asm("mov.b64 {%0, %1}, %2;" : "=f"(lo), "=f"(hi) : "l"(v));
}
__device__ __forceinline__ u64t fma2(u64t a, u64t b, u64t c) {
    u64t d; asm("fma.rn.f32x2 %0, %1, %2, %3;" : "=l"(d) : "l"(a), "l"(b), "l"(c)); return d;
}
__device__ __forceinline__ u64t mul2(u64t a, u64t b) {
    u64t d; asm("mul.rn.f32x2 %0, %1, %2;" : "=l"(d) : "l"(a), "l"(b)); return d;
}
__device__ __forceinline__ u64t add2(u64t a, u64t b) {
    u64t d; asm("add.rn.f32x2 %0, %1, %2;" : "=l"(d) : "l"(a), "l"(b)); return d;
}
__device__ __forceinline__ uint32_t bf16x2_of(float lo, float hi) {
    uint32_t r; asm("cvt.rn.bf16x2.f32 %0, %1, %2;" : "=r"(r) : "f"(hi), "f"(lo)); return r;
}
__device__ __forceinline__ void mma_16816(float c[4], uint32_t a0, uint32_t a1,
                                          uint32_t a2, uint32_t a3,
                                          uint32_t b0, uint32_t b1) {
    asm volatile(
        "mma.sync.aligned.m16n8k16.row.col.f32.bf16.bf16.f32 "
        "{%0,%1,%2,%3}, {%4,%5,%6,%7}, {%8,%9}, {%0,%1,%2,%3};"
        : "+f"(c[0]), "+f"(c[1]), "+f"(c[2]), "+f"(c[3])
        : "r"(a0), "r"(a1), "r"(a2), "r"(a3), "r"(b0), "r"(b1));
}

__global__ __launch_bounds__(128, 8)
void depatch_kernel(const float* __restrict__ x,
                    const float* __restrict__ w1,
                    const float* __restrict__ b1,
                    const float* __restrict__ w2,
                    const float* __restrict__ b2,
                    float* __restrict__ out)
{
    __shared__ __align__(16) float          s_row[L_ + 4];      // fp32 + pad
    __shared__ __align__(16) __nv_bfloat16  s_xbf[L_ + 16];     // bf16 (+pad)
    __shared__ __align__(16) float          s_b1[H_];           // plain b1
    __shared__ __align__(16) float2         s_ld[4][2][2][8];   // [wid][buf][parity][idx]

    const int tid  = threadIdx.x;       // 0..127
    const int wid  = tid >> 5;          // 0..3
    const int lane = tid & 31;
    const int bc   = blockIdx.x;
    const int g    = lane >> 2;         // MMA group id
    const int t    = lane & 3;          // thread within group

    // ---- stage row: fp32 + bf16 in one pass (8 float4 per thread) ----
    {
        const float4* xr = (const float4*)(x + (size_t)bc * L_);
        float4* sr = (float4*)s_row;
        uint2*  sb = (uint2*)s_xbf;
        #pragma unroll
        for (int j = 0; j < 8; j++) {
            const int idx = tid + 128 * j;
            float4 q = xr[idx];
            sr[idx] = q;
            uint2 pr;
            pr.x = bf16x2_of(q.x, q.y);
            pr.y = bf16x2_of(q.z, q.w);
            sb[idx] = pr;
        }
        if (tid < 4) {
            s_row[L_ + tid] = 0.f;
            ((uint32_t*)(s_xbf + L_))[tid] = 0;
        }
    }
    if (tid < H_) s_b1[tid] = b1[tid];
    const float b20 = b2[0];
    const float b21 = b2[1];

    // ---- stage-1 B fragments (w1 [64x16]) ----
    uint32_t bf1[8][2];
    #pragma unroll
    for (int nt = 0; nt < 8; nt++) {
        const float* wr = w1 + (nt * 8 + g) * 16;
        float2 lo = *(const float2*)(wr + 2 * t);
        float2 hi = *(const float2*)(wr + 2 * t + 8);
        bf1[nt][0] = bf16x2_of(lo.x, lo.y);
        bf1[nt][1] = bf16x2_of(hi.x, hi.y);
    }
    // ---- stage-2 B fragments (w2^T [64x2] padded to n=8) ----
    uint32_t bf2[4][2];
    #pragma unroll
    for (int m = 0; m < 4; m++) {
        float v0 = 0.f, v1 = 0.f, v2 = 0.f, v3 = 0.f;
        if (g < 2) {
            const float* wr = w2 + g * H_ + 16 * m;
            v0 = wr[2 * t];     v1 = wr[2 * t + 1];
            v2 = wr[2 * t + 8]; v3 = wr[2 * t + 9];
        }
        bf2[m][0] = bf16x2_of(v0, v1);
        bf2[m][1] = bf16x2_of(v2, v3);
    }

    // GELU: g = h*(0.5 + h*R(h^2)), R = r0 + r1 s
    const u64t r0p = pack2( 0.3989422804f,  0.3989422804f);
    const u64t r1p = pack2(-0.0664903800f, -0.0664903800f);
    const u64t halfp = pack2(0.5f, 0.5f);

    __syncthreads();

    // gather lane roles (conflict-free mapping)
    const int ie  = lane & 15;
    const int hb  = lane >> 4;
    const float tc = (float)ie * (1.0f / 15.0f);
    float* obase0 = out + ((size_t)bc * PC_ + hb) * P_ + ie;

    // prime A fragments for it = 0
    const int abstride = 2 * t;
    {
        const __nv_bfloat16* abit = s_xbf + (wid * 128 + g) * 8 + abstride;
        // loaded below into a0..a3
    }
    const __nv_bfloat16* abit = s_xbf + (wid * 128 + g) * 8 + abstride;
    uint32_t a0 = *(const uint32_t*)(abit);
    uint32_t a1 = *(const uint32_t*)(abit + 64);
    uint32_t a2 = *(const uint32_t*)(abit + 8);
    uint32_t a3 = *(const uint32_t*)(abit + 72);

    // ---- main loop: warp handles 8 blocks of 16 patches ----
    #pragma unroll 1
    for (int it = 0; it < 8; it++) {
        const int p0  = (wid * 8 + it) * 16;
        const int buf = it & 1;

        // per-m production: 2 stage-1 MMAs -> GELU -> 1 stage-2 MMA
        float d0[4] = {0.f, 0.f, 0.f, 0.f};
        float d1[4] = {0.f, 0.f, 0.f, 0.f};
        #pragma unroll
        for (int m = 0; m < 4; m++) {
            uint32_t af[4];
            #pragma unroll
            for (int s = 0; s < 2; s++) {
                const int nt = 2 * m + s;
                float c[4] = {0.f, 0.f, 0.f, 0.f};
                mma_16816(c, a0, a1, a2, a3, bf1[nt][0], bf1[nt][1]);

                const int o0 = nt * 8 + 2 * t;
                const u64t bia = *(const u64t*)(s_b1 + o0);
                u64t hp0 = add2(pack2(c[0], c[1]), bia);   // row g, cols o0,o0+1
                u64t hp1 = add2(pack2(c[2], c[3]), bia);   // row g+8
                u64t s0 = mul2(hp0, hp0);
                u64t R0 = fma2(r1p, s0, r0p);
                u64t i0 = fma2(hp0, R0, halfp);
                u64t g0 = mul2(hp0, i0);
                u64t s1 = mul2(hp1, hp1);
                u64t R1 = fma2(r1p, s1, r0p);
                u64t i1 = fma2(hp1, R1, halfp);
                u64t g1 = mul2(hp1, i1);

                float gl, gh;
                unpack2(g0, gl, gh);
                af[s] = bf16x2_of(gl, gh);
                unpack2(g1, gl, gh);
                af[2 + s] = bf16x2_of(gl, gh);
            }
            mma_16816((m < 2) ? d0 : d1, af[0], af[2], af[1], af[3],
                      bf2[m][0], bf2[m][1]);
        }

        // prefetch next iteration's A fragments (hidden under gather)
        if (it < 7) {
            const __nv_bfloat16* abn = s_xbf + (p0 + 16 + g) * 8 + abstride;
            a0 = *(const uint32_t*)(abn);
            a1 = *(const uint32_t*)(abn + 64);
            a2 = *(const uint32_t*)(abn + 8);
            a3 = *(const uint32_t*)(abn + 72);
        }

        // coord math: t==0 lanes hold rel for patches g and g+8
        if (t == 0) {
            #pragma unroll
            for (int k = 0; k < 2; k++) {
                const int qq = g + 8 * k;
                const int p  = p0 + qq;
                const float dx = (d0[2 * k]     + d1[2 * k])     + b20;
                const float ds = fmaxf(((d0[2 * k + 1] + d1[2 * k + 1]) + b21) + 7.5f, 0.0f);
                const float anchor = (float)p * 8.0f + 7.5f;
                const float lop = fminf(fmaxf((dx + anchor) - ds, 0.0f), 4095.0f);
                const float hip = fminf(fmaxf((dx + anchor) + ds, 0.0f), 4095.0f);
                s_ld[wid][buf][qq & 1][qq >> 1] = make_float2(lop, hip - lop);
            }
        }
        __syncwarp();

        // conflict-free gather: lane owns element ie of patches q = 2e + hb.
        // parity layout -> 4x LDS.128 fetch all 8 coord pairs.
        float4 cp[4];
        #pragma unroll
        for (int j = 0; j < 4; j++)
            cp[j] = *(const float4*)&s_ld[wid][buf][hb][2 * j];

        const bool w7 = (hb == 0) || (p0 != 496);   // only p==511 skipped
        float* ob = obase0 + (size_t)p0 * P_;
        #pragma unroll
        for (int e = 0; e < 8; e++) {
            const float lo  = (e & 1) ? cp[e >> 1].z : cp[e >> 1].x;
            const float dlh = (e & 1) ? cp[e >> 1].w : cp[e >> 1].y;
            const float px = fmaf(dlh, tc, lo);              // in [0, 4095]
            const float fb = __fadd_rz(px, 8388608.0f);      // 2^23 magic floor
            const int   ix = __float_as_int(fb) - 0x4B000000;
            const float fl = fb - 8388608.0f;                // exact floor(px)
            const float wx = px - fl;
            const float va = s_row[ix];
            const float vb = s_row[ix + 1];                  // ix=4095 -> pad 0
            const float res = fmaf(wx, vb - va, va);
            if (e != 7 || w7)
                ob[e * 2 * P_] = res;
        }
    }
}

extern "C" void kernel_launch(void* const* d_in, const int* in_sizes, int n_in,
                              void* d_out, int out_size)
{
    const float* x  = (const float*)d_in[0];
    const float* w1 = (const float*)d_in[1];
    const float* b1 = (const float*)d_in[2];
    const float* w2 = (const float*)d_in[3];
    const float* b2 = (const float*)d_in[4];
    float* out = (float*)d_out;

    depatch_kernel<<<B_ * C_, 128>>>(x, w1, b1, w2, b2, out);
}

// round 15
// speedup vs baseline: 1.0015x; 1.0015x over previous
#include <cuda_runtime.h>
#include <cuda_bf16.h>
#include <cstdint>

// DepatchSampling: B=8, C=128, L=4096, P=16, S=8, PC=511, H=64
// R15 = R14 (21.0us) with the GELU/repack block moved to native bf16x2 math:
//  cvt(accum) -> bias fma.bf16x2 -> 4-op polynomial -> result IS the stage-2
//  A-fragment. Kills all f32x2 pack/unpack movs (~65 slots/iter, ~25%).
//  g was already bf16-rounded before stage-2, so precision cost is ~3 extra
//  bf16 roundings at the same ulp scale (predicted rel_err ~3-5e-4 < 1e-3).

#define B_  8
#define C_  128
#define L_  4096
#define P_  16
#define S_  8
#define PC_ 511
#define H_  64

__device__ __forceinline__ uint32_t bf16x2_of(float lo, float hi) {
    uint32_t r; asm("cvt.rn.bf16x2.f32 %0, %1, %2;" : "=r"(r) : "f"(hi), "f"(lo)); return r;
}
__device__ __forceinline__ uint32_t mul_bf2(uint32_t a, uint32_t b) {
    uint32_t d; asm("mul.rn.bf16x2 %0, %1, %2;" : "=r"(d) : "r"(a), "r"(b)); return d;
}
__device__ __forceinline__ uint32_t fma_bf2(uint32_t a, uint32_t b, uint32_t c) {
    uint32_t d; asm("fma.rn.bf16x2 %0, %1, %2, %3;" : "=r"(d) : "r"(a), "r"(b), "r"(c)); return d;
}
__device__ __forceinline__ void mma_16816(float c[4], uint32_t a0, uint32_t a1,
                                          uint32_t a2, uint32_t a3,
                                          uint32_t b0, uint32_t b1) {
    asm volatile(
        "mma.sync.aligned.m16n8k16.row.col.f32.bf16.bf16.f32 "
        "{%0,%1,%2,%3}, {%4,%5,%6,%7}, {%8,%9}, {%0,%1,%2,%3};"
        : "+f"(c[0]), "+f"(c[1]), "+f"(c[2]), "+f"(c[3])
        : "r"(a0), "r"(a1), "r"(a2), "r"(a3), "r"(b0), "r"(b1));
}

__global__ __launch_bounds__(128, 8)
void depatch_kernel(const float* __restrict__ x,
                    const float* __restrict__ w1,
                    const float* __restrict__ b1,
                    const float* __restrict__ w2,
                    const float* __restrict__ b2,
                    float* __restrict__ out)
{
    __shared__ __align__(16) float          s_row[L_ + 4];      // fp32 + pad
    __shared__ __align__(16) __nv_bfloat16  s_xbf[L_ + 16];     // bf16 (+pad)
    __shared__ __align__(16) uint32_t       s_b1b[H_ / 2];      // b1 as bf16x2 pairs
    __shared__ __align__(16) float2         s_ld[4][2][2][8];   // [wid][buf][parity][idx]

    const int tid  = threadIdx.x;       // 0..127
    const int wid  = tid >> 5;          // 0..3
    const int lane = tid & 31;
    const int bc   = blockIdx.x;
    const int g    = lane >> 2;         // MMA group id
    const int t    = lane & 3;          // thread within group

    // ---- stage row: fp32 + bf16 in one pass (8 float4 per thread) ----
    {
        const float4* xr = (const float4*)(x + (size_t)bc * L_);
        float4* sr = (float4*)s_row;
        uint2*  sb = (uint2*)s_xbf;
        #pragma unroll
        for (int j = 0; j < 8; j++) {
            const int idx = tid + 128 * j;
            float4 q = xr[idx];
            sr[idx] = q;
            uint2 pr;
            pr.x = bf16x2_of(q.x, q.y);
            pr.y = bf16x2_of(q.z, q.w);
            sb[idx] = pr;
        }
        if (tid < 4) {
            s_row[L_ + tid] = 0.f;
            ((uint32_t*)(s_xbf + L_))[tid] = 0;
        }
    }
    if (tid < H_ / 2) {
        float2 bv = ((const float2*)b1)[tid];
        s_b1b[tid] = bf16x2_of(bv.x, bv.y);
    }
    const float b20 = b2[0];
    const float b21 = b2[1];

    // ---- stage-1 B fragments (w1 [64x16]) ----
    uint32_t bf1[8][2];
    #pragma unroll
    for (int nt = 0; nt < 8; nt++) {
        const float* wr = w1 + (nt * 8 + g) * 16;
        float2 lo = *(const float2*)(wr + 2 * t);
        float2 hi = *(const float2*)(wr + 2 * t + 8);
        bf1[nt][0] = bf16x2_of(lo.x, lo.y);
        bf1[nt][1] = bf16x2_of(hi.x, hi.y);
    }
    // ---- stage-2 B fragments (w2^T [64x2] padded to n=8) ----
    uint32_t bf2[4][2];
    #pragma unroll
    for (int m = 0; m < 4; m++) {
        float v0 = 0.f, v1 = 0.f, v2 = 0.f, v3 = 0.f;
        if (g < 2) {
            const float* wr = w2 + g * H_ + 16 * m;
            v0 = wr[2 * t];     v1 = wr[2 * t + 1];
            v2 = wr[2 * t + 8]; v3 = wr[2 * t + 9];
        }
        bf2[m][0] = bf16x2_of(v0, v1);
        bf2[m][1] = bf16x2_of(v2, v3);
    }

    // GELU (bf16x2): g = h*(0.5 + h*R(h^2)), R = r0 + r1*s
    const uint32_t r0b   = bf16x2_of( 0.3989422804f,  0.3989422804f);
    const uint32_t r1b   = bf16x2_of(-0.0664903800f, -0.0664903800f);
    const uint32_t halfb = bf16x2_of(0.5f, 0.5f);
    const uint32_t oneb  = bf16x2_of(1.0f, 1.0f);

    __syncthreads();

    // gather lane roles (conflict-free mapping)
    const int ie  = lane & 15;
    const int hb  = lane >> 4;
    const float tc = (float)ie * (1.0f / 15.0f);
    float* obase0 = out + ((size_t)bc * PC_ + hb) * P_ + ie;

    // prime A fragments for it = 0
    const int abstride = 2 * t;
    const __nv_bfloat16* abit = s_xbf + (wid * 128 + g) * 8 + abstride;
    uint32_t a0 = *(const uint32_t*)(abit);
    uint32_t a1 = *(const uint32_t*)(abit + 64);
    uint32_t a2 = *(const uint32_t*)(abit + 8);
    uint32_t a3 = *(const uint32_t*)(abit + 72);

    // ---- main loop: warp handles 8 blocks of 16 patches ----
    #pragma unroll 1
    for (int it = 0; it < 8; it++) {
        const int p0  = (wid * 8 + it) * 16;
        const int buf = it & 1;

        // per-m production: 2 stage-1 MMAs -> bf16 GELU -> 1 stage-2 MMA
        float d0[4] = {0.f, 0.f, 0.f, 0.f};
        float d1[4] = {0.f, 0.f, 0.f, 0.f};
        #pragma unroll
        for (int m = 0; m < 4; m++) {
            uint32_t af[4];
            #pragma unroll
            for (int s = 0; s < 2; s++) {
                const int nt = 2 * m + s;
                float c[4] = {0.f, 0.f, 0.f, 0.f};
                mma_16816(c, a0, a1, a2, a3, bf1[nt][0], bf1[nt][1]);

                const uint32_t bia = s_b1b[nt * 4 + t];      // {b1[o0], b1[o0+1]}
                // h pairs in bf16x2: low = col o0, high = col o0+1
                uint32_t h0 = fma_bf2(bf16x2_of(c[0], c[1]), oneb, bia);  // row g
                uint32_t h1 = fma_bf2(bf16x2_of(c[2], c[3]), oneb, bia);  // row g+8
                uint32_t s0 = mul_bf2(h0, h0);
                uint32_t R0 = fma_bf2(s0, r1b, r0b);
                uint32_t i0 = fma_bf2(h0, R0, halfb);
                af[s]       = mul_bf2(h0, i0);               // = gelu, already bf16x2
                uint32_t s1 = mul_bf2(h1, h1);
                uint32_t R1 = fma_bf2(s1, r1b, r0b);
                uint32_t i1 = fma_bf2(h1, R1, halfb);
                af[2 + s]   = mul_bf2(h1, i1);
            }
            mma_16816((m < 2) ? d0 : d1, af[0], af[2], af[1], af[3],
                      bf2[m][0], bf2[m][1]);
        }

        // prefetch next iteration's A fragments (hidden under gather)
        if (it < 7) {
            const __nv_bfloat16* abn = s_xbf + (p0 + 16 + g) * 8 + abstride;
            a0 = *(const uint32_t*)(abn);
            a1 = *(const uint32_t*)(abn + 64);
            a2 = *(const uint32_t*)(abn + 8);
            a3 = *(const uint32_t*)(abn + 72);
        }

        // coord math: t==0 lanes hold rel for patches g and g+8
        if (t == 0) {
            #pragma unroll
            for (int k = 0; k < 2; k++) {
                const int qq = g + 8 * k;
                const int p  = p0 + qq;
                const float dx = (d0[2 * k]     + d1[2 * k])     + b20;
                const float ds = fmaxf(((d0[2 * k + 1] + d1[2 * k + 1]) + b21) + 7.5f, 0.0f);
                const float anchor = (float)p * 8.0f + 7.5f;
                const float lop = fminf(fmaxf((dx + anchor) - ds, 0.0f), 4095.0f);
                const float hip = fminf(fmaxf((dx + anchor) + ds, 0.0f), 4095.0f);
                s_ld[wid][buf][qq & 1][qq >> 1] = make_float2(lop, hip - lop);
            }
        }
        __syncwarp();

        // conflict-free gather: lane owns element ie of patches q = 2e + hb.
        float4 cp[4];
        #pragma unroll
        for (int j = 0; j < 4; j++)
            cp[j] = *(const float4*)&s_ld[wid][buf][hb][2 * j];

        const bool w7 = (hb == 0) || (p0 != 496);   // only p==511 skipped
        float* ob = obase0 + (size_t)p0 * P_;
        #pragma unroll
        for (int e = 0; e < 8; e++) {
            const float lo  = (e & 1) ? cp[e >> 1].z : cp[e >> 1].x;
            const float dlh = (e & 1) ? cp[e >> 1].w : cp[e >> 1].y;
            const float px = fmaf(dlh, tc, lo);              // in [0, 4095]
            const float fb = __fadd_rz(px, 8388608.0f);      // 2^23 magic floor
            const int   ix = __float_as_int(fb) - 0x4B000000;
            const float fl = fb - 8388608.0f;                // exact floor(px)
            const float wx = px - fl;
            const float va = s_row[ix];
            const float vb = s_row[ix + 1];                  // ix=4095 -> pad 0
            const float res = fmaf(wx, vb - va, va);
            if (e != 7 || w7)
                ob[e * 2 * P_] = res;
        }
    }
}

extern "C" void kernel_launch(void* const* d_in, const int* in_sizes, int n_in,
                              void* d_out, int out_size)
{
    const float* x  = (const float*)d_in[0];
    const float* w1 = (const float*)d_in[1];
    const float* b1 = (const float*)d_in[2];
    const float* w2 = (const float*)d_in[3];
    const float* b2 = (const float*)d_in[4];
    float* out = (float*)d_out;

    depatch_kernel<<<B_ * C_, 128>>>(x, w1, b1, w2, b2, out);
}